// round 16
// baseline (speedup 1.0000x reference)
#include <cuda_runtime.h>
#include <cuda_fp16.h>
#include <math.h>
#include <cstdint>

#define SEQ   2048
#define BATCH 2
#define NH    16
#define HD    64
#define EMB   1024
#define E3    3072
#define NROWS (BATCH*SEQ)          // 4096
#define NBIAS (2*SEQ-1)            // 4095
#define NBP   4096
#define L2E   1.4426950408889634f

// ---------------- scratch (__device__ globals) ------------------------------
__device__ __half g_ah[(size_t)NROWS * EMB];
__device__ __half g_al[(size_t)NROWS * EMB];
__device__ __half g_wqh[(size_t)EMB * E3];
__device__ __half g_wql[(size_t)EMB * E3];
__device__ __half g_woh[(size_t)EMB * EMB];
__device__ __half g_qkv_h[(size_t)NROWS * E3];
__device__ __half g_qkv_l[(size_t)NROWS * E3];
__device__ __half g_attn_h[(size_t)NROWS * EMB];
__device__ float g_bias[NH * NBP];

// ---------------- PTX helpers ----------------------------------------------
__device__ __forceinline__ uint32_t smem_u32(const void* p) {
    uint32_t a;
    asm("{ .reg .u64 t; cvta.to.shared.u64 t, %1; cvt.u32.u64 %0, t; }" : "=r"(a) : "l"(p));
    return a;
}
#define LDSM_X4(r, a) \
    asm volatile("ldmatrix.sync.aligned.m8n8.x4.shared.b16 {%0,%1,%2,%3}, [%4];" \
        : "=r"((r)[0]), "=r"((r)[1]), "=r"((r)[2]), "=r"((r)[3]) : "r"(a))
#define LDSM_X4T(r, a) \
    asm volatile("ldmatrix.sync.aligned.m8n8.x4.trans.shared.b16 {%0,%1,%2,%3}, [%4];" \
        : "=r"((r)[0]), "=r"((r)[1]), "=r"((r)[2]), "=r"((r)[3]) : "r"(a))
#define MMA16816(d, a, b0, b1) \
    asm volatile("mma.sync.aligned.m16n8k16.row.col.f32.f16.f16.f32 " \
        "{%0,%1,%2,%3}, {%4,%5,%6,%7}, {%8,%9}, {%0,%1,%2,%3};" \
        : "+f"((d)[0]), "+f"((d)[1]), "+f"((d)[2]), "+f"((d)[3]) \
        : "r"((a)[0]), "r"((a)[1]), "r"((a)[2]), "r"((a)[3]), "r"(b0), "r"(b1))
#define CP16(d, s) asm volatile("cp.async.cg.shared.global [%0], [%1], 16;" :: "r"(d), "l"(s))
#define CP_COMMIT() asm volatile("cp.async.commit_group;" ::: "memory")
#define CP_WAIT0()  asm volatile("cp.async.wait_group 0;" ::: "memory")
#define CP_WAIT1()  asm volatile("cp.async.wait_group 1;" ::: "memory")

__device__ __forceinline__ float ex2a(float x) {
    float r; asm("ex2.approx.ftz.f32 %0, %1;" : "=f"(r) : "f"(x)); return r;
}
__device__ __forceinline__ float rcpa(float x) {
    float r; asm("rcp.approx.ftz.f32 %0, %1;" : "=f"(r) : "f"(x)); return r;
}
__device__ __forceinline__ uint32_t h2ex2(uint32_t x) {
    uint32_t r; asm("ex2.approx.f16x2 %0, %1;" : "=r"(r) : "r"(x)); return r;
}

__device__ __forceinline__ void cvt_split2h(float x, float y, uint32_t& h, uint32_t& l) {
    __half hx = __float2half(x);
    __half hy = __float2half(y);
    __half lx = __float2half(x - __half2float(hx));
    __half ly = __float2half(y - __half2float(hy));
    h = (uint32_t)__half_as_ushort(hx) | ((uint32_t)__half_as_ushort(hy) << 16);
    l = (uint32_t)__half_as_ushort(lx) | ((uint32_t)__half_as_ushort(ly) << 16);
}
__device__ __forceinline__ uint32_t cvt2h(float x, float y) {
    return (uint32_t)__half_as_ushort(__float2half(x)) |
           ((uint32_t)__half_as_ushort(__float2half(y)) << 16);
}

// ---------------------------------------------------------------------------
// Merged prepass: split hidden + W_qkv, convert W_out, build bias table.
// ---------------------------------------------------------------------------
#define P1 (NROWS*EMB/4)
#define P2 (EMB*E3/4)
#define P3 (EMB*EMB/4)
#define PTOT (P1+P2+P3)

__global__ void prep_kernel(const float* __restrict__ hidden,
                            const float* __restrict__ wq,
                            const float* __restrict__ wo,
                            const float* __restrict__ rel_emb) {
    int i = blockIdx.x * blockDim.x + threadIdx.x;
    if (i < P1) {
        float4 a = ((const float4*)hidden)[i];
        uint32_t h01, l01, h23, l23;
        cvt_split2h(a.x, a.y, h01, l01);
        cvt_split2h(a.z, a.w, h23, l23);
        ((uint2*)g_ah)[i] = make_uint2(h01, h23);
        ((uint2*)g_al)[i] = make_uint2(l01, l23);
    } else if (i < P1 + P2) {
        int j = i - P1;
        float4 a = ((const float4*)wq)[j];
        uint32_t h01, l01, h23, l23;
        cvt_split2h(a.x, a.y, h01, l01);
        cvt_split2h(a.z, a.w, h23, l23);
        ((uint2*)g_wqh)[j] = make_uint2(h01, h23);
        ((uint2*)g_wql)[j] = make_uint2(l01, l23);
    } else if (i < PTOT) {
        int j = i - P1 - P2;
        float4 a = ((const float4*)wo)[j];
        ((uint2*)g_woh)[j] = make_uint2(cvt2h(a.x, a.y), cvt2h(a.z, a.w));
    } else {
        int j = i - PTOT;
        if (j >= NBIAS) return;
        int d  = j - (SEQ - 1);
        int rb = (d > 0) ? 16 : 0;
        int ad = d < 0 ? -d : d;
        int bucket;
        if (ad < 8) bucket = ad;
        else {
            float v  = logf((float)ad * 0.125f) / 2.7725887f;
            int   lg = 8 + (int)(v * 8.0f);
            bucket = lg < 15 ? lg : 15;
        }
        int idx = rb + bucket;
        #pragma unroll
        for (int h = 0; h < NH; h++)
            g_bias[h * NBP + j] = rel_emb[idx * NH + h];
    }
}

// ---------------------------------------------------------------------------
// Pipelined fp16 GEMM body. TERMS in {1,2,3}; STAGES in {2,3}.
// ---------------------------------------------------------------------------
template<int TERMS>
struct GLay {
    static constexpr uint32_t AH = 0;
    static constexpr uint32_t AL = 10240;
    static constexpr uint32_t BH = (TERMS >= 2) ? 20480 : 10240;
    static constexpr uint32_t BL = BH + 8704;
    static constexpr uint32_t SSZ = BH + 8704u * (TERMS == 3 ? 2 : 1);
};

#define QKV_SMEM 87552u
#define OUT_SMEM 56832u

template<int TERMS>
__device__ __forceinline__ void gemm_issue(
    uint32_t base, const __half* Ah, const __half* Al,
    const __half* Bh, const __half* Bl,
    int k0, int K, int N, int tid)
{
    using L = GLay<TERMS>;
    #pragma unroll
    for (int t = 0; t < 2; t++) {
        int i = tid + t * 256;
        int r = i >> 2, c = i & 3;
        uint32_t off = r * 80 + c * 16;
        size_t so = (size_t)r * K + k0 + c * 8;
        CP16(base + L::AH + off, Ah + so);
        if (TERMS >= 2) CP16(base + L::AL + off, Al + so);
    }
    #pragma unroll
    for (int t = 0; t < 2; t++) {
        int i = tid + t * 256;
        int r = i >> 4, c = i & 15;
        uint32_t off = r * 272 + c * 16;
        size_t so = (size_t)(k0 + r) * N + c * 8;
        CP16(base + L::BH + off, Bh + so);
        if (TERMS == 3) CP16(base + L::BL + off, Bl + so);
    }
}

template<int TERMS, int STAGES>
__device__ __forceinline__ void gemm_body(
    const __half* __restrict__ Ah, const __half* __restrict__ Al,
    const __half* __restrict__ Bh, const __half* __restrict__ Bl,
    int K, int N, size_t n0, float* __restrict__ Cf,
    __half* __restrict__ Ch, __half* __restrict__ Cl)
{
    using L = GLay<TERMS>;
    extern __shared__ __align__(16) uint8_t smem[];
    const uint32_t sb = smem_u32(smem);
    const int tid = threadIdx.x, wid = tid >> 5, lane = tid & 31;
    const int wm = wid & 3, wn = wid >> 2;
    const size_t m0 = (size_t)blockIdx.y * 128;

    const __half* Ahp = Ah + m0 * K;
    const __half* Alp = (TERMS >= 2) ? (Al + m0 * K) : nullptr;
    const __half* Bhp = Bh + n0;
    const __half* Blp = (TERMS == 3) ? (Bl + n0) : nullptr;

    float acc[2][8][4];
    #pragma unroll
    for (int i = 0; i < 2; i++)
        #pragma unroll
        for (int j = 0; j < 8; j++)
            #pragma unroll
            for (int r = 0; r < 4; r++) acc[i][j][r] = 0.f;

    const uint32_t a_fb = (wm * 32 + (lane & 15)) * 80 + (lane >> 4) * 16;
    const uint32_t b_fb = L::BH + (lane & 15) * 272 + wn * 128 + (lane >> 4) * 16;

    const int niter = K >> 5;
    #pragma unroll
    for (int p = 0; p < STAGES - 1; p++) {
        gemm_issue<TERMS>(sb + p * L::SSZ, Ahp, Alp, Bhp, Blp, p << 5, K, N, tid);
        CP_COMMIT();
    }

    for (int it = 0; it < niter; it++) {
        if (STAGES == 3 && it + 2 <= niter) CP_WAIT1(); else CP_WAIT0();
        __syncthreads();
        if (it + STAGES - 1 < niter) {
            gemm_issue<TERMS>(sb + ((it + STAGES - 1) % STAGES) * L::SSZ,
                              Ahp, Alp, Bhp, Blp, (it + STAGES - 1) << 5, K, N, tid);
            CP_COMMIT();
        }
        const uint32_t st = sb + (it % STAGES) * L::SSZ;

        #pragma unroll
        for (int ks = 0; ks < 2; ks++) {
            uint32_t ah[2][4], al[2][4];
            #pragma unroll
            for (int i = 0; i < 2; i++) {
                uint32_t aa = st + a_fb + i * 16 * 80 + ks * 32;
                LDSM_X4(ah[i], aa + L::AH);
                if (TERMS >= 2) LDSM_X4(al[i], aa + L::AL);
            }
            #pragma unroll
            for (int nh = 0; nh < 2; nh++) {
                #pragma unroll
                for (int j16 = 0; j16 < 2; j16++) {
                    uint32_t ba = st + b_fb + ks * 16 * 272 + nh * 64 + j16 * 32;
                    uint32_t bh[4];
                    LDSM_X4T(bh, ba);
                    int nf = nh * 4 + j16 * 2;
                    #pragma unroll
                    for (int i = 0; i < 2; i++) {
                        MMA16816(acc[i][nf],     ah[i], bh[0], bh[1]);
                        MMA16816(acc[i][nf + 1], ah[i], bh[2], bh[3]);
                        if (TERMS >= 2) {
                            MMA16816(acc[i][nf],     al[i], bh[0], bh[1]);
                            MMA16816(acc[i][nf + 1], al[i], bh[2], bh[3]);
                        }
                    }
                    if (TERMS == 3) {
                        uint32_t bl[4];
                        LDSM_X4T(bl, ba + (L::BL - L::BH));
                        #pragma unroll
                        for (int i = 0; i < 2; i++) {
                            MMA16816(acc[i][nf],     ah[i], bl[0], bl[1]);
                            MMA16816(acc[i][nf + 1], ah[i], bl[2], bl[3]);
                        }
                    }
                }
            }
        }
    }

    const int row_in = lane >> 2, col_in = (lane & 3) * 2;
    if (Cf) {
        #pragma unroll
        for (int i = 0; i < 2; i++)
            #pragma unroll
            for (int nf = 0; nf < 8; nf++) {
                float* p = Cf + (m0 + wm * 32 + i * 16 + row_in) * N + n0 + wn * 64 + nf * 8 + col_in;
                *(float2*)p                   = make_float2(acc[i][nf][0], acc[i][nf][1]);
                *(float2*)(p + 8 * (size_t)N) = make_float2(acc[i][nf][2], acc[i][nf][3]);
            }
    } else {
        #pragma unroll
        for (int i = 0; i < 2; i++)
            #pragma unroll
            for (int nf = 0; nf < 8; nf++) {
                size_t o = (m0 + wm * 32 + i * 16 + row_in) * N + n0 + wn * 64 + nf * 8 + col_in;
                uint32_t h01, l01, h23, l23;
                cvt_split2h(acc[i][nf][0], acc[i][nf][1], h01, l01);
                cvt_split2h(acc[i][nf][2], acc[i][nf][3], h23, l23);
                *(uint32_t*)(Ch + o) = h01;
                *(uint32_t*)(Ch + o + 8 * (size_t)N) = h23;
                if (Cl) {
                    *(uint32_t*)(Cl + o) = l01;
                    *(uint32_t*)(Cl + o + 8 * (size_t)N) = l23;
                }
            }
    }
}

__global__ __launch_bounds__(256, 2) void qkv_kernel(
    const __half* __restrict__ Ah, const __half* __restrict__ Al,
    const __half* __restrict__ Bh, const __half* __restrict__ Bl,
    __half* __restrict__ Ch, __half* __restrict__ Cl)
{
    size_t n0 = (size_t)blockIdx.x * 128;
    if (blockIdx.x < 16)
        gemm_body<3, 2>(Ah, Al, Bh, Bl, EMB, E3, n0, nullptr, Ch, Cl);
    else
        gemm_body<2, 3>(Ah, Al, Bh, nullptr, EMB, E3, n0, nullptr, Ch, nullptr);
}

__global__ __launch_bounds__(256, 2) void outproj_kernel(
    const __half* __restrict__ Ah, const __half* __restrict__ Bh,
    float* __restrict__ Cf)
{
    gemm_body<1, 3>(Ah, nullptr, Bh, nullptr, EMB, EMB,
                    (size_t)blockIdx.x * 128, Cf, nullptr, nullptr);
}

// ---------------------------------------------------------------------------
// fp16 HMMA flash attention: QK 3-term, PV 1-term.
// Softmax: fp16x2 exponentials; row-sum l via ones-column MMA.
// ---------------------------------------------------------------------------
#define KV_KH 0
#define KV_KL 9216
#define KV_VH 18432
#define KV_BIAS 27648
#define KV_STG 28672
#define AQ_H (2*KV_STG)
#define AQ_L (AQ_H + 18432)
#define ATTN_SMEM (AQ_L + 18432)    // 94208

__device__ __forceinline__ void attn_issue(
    uint32_t base, const __half* kh, const __half* kl, const __half* vh,
    const float* biasrc, int tid)
{
    #pragma unroll
    for (int t = 0; t < 2; t++) {
        int i = tid + t * 256;
        int r = i >> 3, c = i & 7;
        uint32_t off = r * 144 + c * 16;
        size_t so = (size_t)r * E3 + c * 8;
        CP16(base + KV_KH + off, kh + so);
        CP16(base + KV_KL + off, kl + so);
        CP16(base + KV_VH + off, vh + so);
    }
    if (tid < 48) CP16(base + KV_BIAS + tid * 16, biasrc + tid * 4);
}

__global__ __launch_bounds__(256, 2) void attn_mma_kernel() {
    extern __shared__ __align__(16) uint8_t sm8[];
    const uint32_t sb = smem_u32(sm8);
    const int tid = threadIdx.x, wid = tid >> 5, lane = tid & 31;
    const int q0 = blockIdx.x * 128;
    const int b = blockIdx.y >> 4, h = blockIdx.y & 15;
    const size_t rowbase = (size_t)b * SEQ;
    const float* bias_h = g_bias + h * NBP;

    // ---- stage Q hi/lo ----
    const __half* Qh = g_qkv_h + (rowbase + q0) * E3 + h * HD;
    const __half* Ql = g_qkv_l + (rowbase + q0) * E3 + h * HD;
    #pragma unroll
    for (int t = 0; t < 4; t++) {
        int i = tid + t * 256;
        int r = i >> 3, c = i & 7;
        uint32_t off = r * 144 + c * 16;
        size_t so = (size_t)r * E3 + c * 8;
        *(uint4*)(sm8 + AQ_H + off) = *(const uint4*)(Qh + so);
        *(uint4*)(sm8 + AQ_L + off) = *(const uint4*)(Ql + so);
    }

    // ---- prologue ----
    const __half* Kh0 = g_qkv_h + rowbase * E3 + EMB + h * HD;
    const __half* Kl0 = g_qkv_l + rowbase * E3 + EMB + h * HD;
    attn_issue(sb, Kh0, Kl0, Kh0 + EMB, bias_h - q0 + 1920, tid);
    CP_COMMIT();

    __syncthreads();
    uint32_t qh[4][4], ql[4][4];
    {
        uint32_t qa = sb + (wid * 16 + (lane & 15)) * 144 + (lane >> 4) * 16;
        #pragma unroll
        for (int ks = 0; ks < 4; ks++) {
            LDSM_X4(qh[ks], qa + AQ_H + ks * 32);
            LDSM_X4(ql[ks], qa + AQ_L + ks * 32);
        }
    }

    float m0 = -INFINITY, m1 = -INFINITY;
    float o[8][4], ol[4];
    #pragma unroll
    for (int j = 0; j < 8; j++)
        #pragma unroll
        for (int r = 0; r < 4; r++) o[j][r] = 0.f;
    #pragma unroll
    for (int r = 0; r < 4; r++) ol[r] = 0.f;

    // ones-column B fragment (col 0 only): lanes 0..3 hold k-rows of col 0
    const uint32_t bone = ((lane >> 2) == 0) ? 0x3C003C00u : 0u;

    const uint32_t kv_fb = (lane & 15) * 144 + (lane >> 4) * 16;
    const int ccol = (lane & 3) * 2;
    const int r0 = wid * 16 + (lane >> 2);
    const int r1 = r0 + 8;

    for (int kt = 0; kt < SEQ / 64; kt++) {
        CP_WAIT0();
        __syncthreads();
        if (kt + 1 < SEQ / 64) {
            const __half* Khn = g_qkv_h + (rowbase + (kt + 1) * 64) * E3 + EMB + h * HD;
            const __half* Kln = g_qkv_l + (rowbase + (kt + 1) * 64) * E3 + EMB + h * HD;
            attn_issue(sb + ((kt + 1) & 1) * KV_STG, Khn, Kln, Khn + EMB,
                       bias_h + (kt + 1) * 64 - q0 + 1920, tid);
            CP_COMMIT();
        }
        const uint32_t st = sb + (kt & 1) * KV_STG;
        const float* sbias = (const float*)(sm8 + (kt & 1) * KV_STG + KV_BIAS);

        // ---- S = bias + Q @ K^T (3-term) ----
        float s[8][4];
        #pragma unroll
        for (int j = 0; j < 8; j++) {
            int c = j * 8 + ccol;
            s[j][0] = sbias[c - r0 + 127];
            s[j][1] = sbias[c + 1 - r0 + 127];
            s[j][2] = sbias[c - r1 + 127];
            s[j][3] = sbias[c + 1 - r1 + 127];
        }

        #pragma unroll
        for (int ks = 0; ks < 4; ks++) {
            #pragma unroll
            for (int nb = 0; nb < 4; nb++) {
                uint32_t kh[4], kl[4];
                uint32_t ka = st + kv_fb + nb * 16 * 144 + ks * 32;
                LDSM_X4(kh, ka + KV_KH);
                LDSM_X4(kl, ka + KV_KL);
                MMA16816(s[2*nb],   qh[ks], kh[0], kh[2]);
                MMA16816(s[2*nb+1], qh[ks], kh[1], kh[3]);
                MMA16816(s[2*nb],   ql[ks], kh[0], kh[2]);
                MMA16816(s[2*nb+1], ql[ks], kh[1], kh[3]);
                MMA16816(s[2*nb],   qh[ks], kl[0], kl[2]);
                MMA16816(s[2*nb+1], qh[ks], kl[1], kl[3]);
            }
        }

        // ---- running max + rescale ----
        float mx0 = -INFINITY, mx1 = -INFINITY;
        #pragma unroll
        for (int j = 0; j < 8; j++) {
            mx0 = fmaxf(mx0, fmaxf(s[j][0], s[j][1]));
            mx1 = fmaxf(mx1, fmaxf(s[j][2], s[j][3]));
        }
        mx0 = fmaxf(mx0, __shfl_xor_sync(0xffffffffu, mx0, 1));
        mx0 = fmaxf(mx0, __shfl_xor_sync(0xffffffffu, mx0, 2));
        mx1 = fmaxf(mx1, __shfl_xor_sync(0xffffffffu, mx1, 1));
        mx1 = fmaxf(mx1, __shfl_xor_sync(0xffffffffu, mx1, 2));
        float m0n = fmaxf(m0, mx0), m1n = fmaxf(m1, mx1);
        float c0 = ex2a((m0 - m0n) * L2E), c1 = ex2a((m1 - m1n) * L2E);
        m0 = m0n; m1 = m1n;
        ol[0] *= c0; ol[2] *= c1;
        #pragma unroll
        for (int j = 0; j < 8; j++) {
            o[j][0] *= c0; o[j][1] *= c0; o[j][2] *= c1; o[j][3] *= c1;
        }

        // ---- P = exp2 in fp16x2; l += P@1 (MMA); O += P @ V ----
        #pragma unroll
        for (int t = 0; t < 4; t++) {
            uint32_t ap[4];
            ap[0] = h2ex2(cvt2h((s[2*t][0]   - m0n) * L2E, (s[2*t][1]   - m0n) * L2E));
            ap[1] = h2ex2(cvt2h((s[2*t][2]   - m1n) * L2E, (s[2*t][3]   - m1n) * L2E));
            ap[2] = h2ex2(cvt2h((s[2*t+1][0] - m0n) * L2E, (s[2*t+1][1] - m0n) * L2E));
            ap[3] = h2ex2(cvt2h((s[2*t+1][2] - m1n) * L2E, (s[2*t+1][3] - m1n) * L2E));
            MMA16816(ol, ap, bone, bone);
            #pragma unroll
            for (int g = 0; g < 4; g++) {
                uint32_t vh[4];
                LDSM_X4T(vh, st + kv_fb + t * 16 * 144 + g * 32 + KV_VH);
                MMA16816(o[2*g],   ap, vh[0], vh[1]);
                MMA16816(o[2*g+1], ap, vh[2], vh[3]);
            }
        }
    }

    // ---- epilogue: broadcast l from quad leader, normalize, store ----
    float l0 = __shfl_sync(0xffffffffu, ol[0], lane & 0x1c);
    float l1 = __shfl_sync(0xffffffffu, ol[2], lane & 0x1c);
    float inv0 = rcpa(l0), inv1 = rcpa(l1);
    size_t ob = (rowbase + q0 + r0) * EMB + h * HD + ccol;
    #pragma unroll
    for (int j = 0; j < 8; j++) {
        *(uint32_t*)(g_attn_h + ob + j * 8)           = cvt2h(o[j][0] * inv0, o[j][1] * inv0);
        *(uint32_t*)(g_attn_h + ob + 8 * EMB + j * 8) = cvt2h(o[j][2] * inv1, o[j][3] * inv1);
    }
}

// ---------------------------------------------------------------------------
extern "C" void kernel_launch(void* const* d_in, const int* in_sizes, int n_in,
                              void* d_out, int out_size) {
    const float* hidden = (const float*)d_in[0];
    const float* W_qkv  = (const float*)d_in[1];
    const float* W_out  = (const float*)d_in[2];
    const float* rel    = (const float*)d_in[3];
    float* out = (float*)d_out;

    __half *ah, *al, *wqh, *wql, *woh, *qh, *ql, *ath;
    cudaGetSymbolAddress((void**)&ah,  g_ah);
    cudaGetSymbolAddress((void**)&al,  g_al);
    cudaGetSymbolAddress((void**)&wqh, g_wqh);
    cudaGetSymbolAddress((void**)&wql, g_wql);
    cudaGetSymbolAddress((void**)&woh, g_woh);
    cudaGetSymbolAddress((void**)&qh,  g_qkv_h);
    cudaGetSymbolAddress((void**)&ql,  g_qkv_l);
    cudaGetSymbolAddress((void**)&ath, g_attn_h);

    cudaFuncSetAttribute(qkv_kernel,
                         cudaFuncAttributeMaxDynamicSharedMemorySize, QKV_SMEM);
    cudaFuncSetAttribute(outproj_kernel,
                         cudaFuncAttributeMaxDynamicSharedMemorySize, OUT_SMEM);
    cudaFuncSetAttribute(attn_mma_kernel,
                         cudaFuncAttributeMaxDynamicSharedMemorySize, ATTN_SMEM);

    prep_kernel<<<(PTOT + NBIAS + 255) / 256, 256>>>(hidden, W_qkv, W_out, rel);

    qkv_kernel<<<dim3(E3 / 128, NROWS / 128), 256, QKV_SMEM>>>(
        ah, al, wqh, wql, qh, ql);

    attn_mma_kernel<<<dim3(SEQ / 128, BATCH * NH), 256, ATTN_SMEM>>>();

    outproj_kernel<<<dim3(EMB / 128, NROWS / 128), 256, OUT_SMEM>>>(
        ath, woh, out);
}

// round 17
// speedup vs baseline: 1.7431x; 1.7431x over previous
#include <cuda_runtime.h>
#include <cuda_fp16.h>
#include <math.h>
#include <cstdint>

#define SEQ   2048
#define BATCH 2
#define NH    16
#define HD    64
#define EMB   1024
#define E3    3072
#define NROWS (BATCH*SEQ)          // 4096
#define NBIAS (2*SEQ-1)            // 4095
#define NBP   4096
#define L2E   1.4426950408889634f

// ---------------- scratch (__device__ globals) ------------------------------
__device__ __half g_ah[(size_t)NROWS * EMB];    // hidden split hi
__device__ __half g_al[(size_t)NROWS * EMB];    // hidden split lo
__device__ __half g_wqh[(size_t)EMB * E3];      // W_qkv hi
__device__ __half g_wql[(size_t)EMB * E3];      // W_qkv lo (used for Q,K cols)
__device__ __half g_woh[(size_t)EMB * EMB];     // W_out hi only
__device__ __half g_qkv_h[(size_t)NROWS * E3];  // QKV result hi
__device__ __half g_qkv_l[(size_t)NROWS * E3];  // QKV result lo (Q,K cols)
__device__ __half g_attn_h[(size_t)NROWS * EMB];
__device__ float g_bias[NH * NBP];

// ---------------- PTX helpers ----------------------------------------------
__device__ __forceinline__ uint32_t smem_u32(const void* p) {
    uint32_t a;
    asm("{ .reg .u64 t; cvta.to.shared.u64 t, %1; cvt.u32.u64 %0, t; }" : "=r"(a) : "l"(p));
    return a;
}
#define LDSM_X4(r, a) \
    asm volatile("ldmatrix.sync.aligned.m8n8.x4.shared.b16 {%0,%1,%2,%3}, [%4];" \
        : "=r"((r)[0]), "=r"((r)[1]), "=r"((r)[2]), "=r"((r)[3]) : "r"(a))
#define LDSM_X4T(r, a) \
    asm volatile("ldmatrix.sync.aligned.m8n8.x4.trans.shared.b16 {%0,%1,%2,%3}, [%4];" \
        : "=r"((r)[0]), "=r"((r)[1]), "=r"((r)[2]), "=r"((r)[3]) : "r"(a))
#define MMA16816(d, a, b0, b1) \
    asm volatile("mma.sync.aligned.m16n8k16.row.col.f32.f16.f16.f32 " \
        "{%0,%1,%2,%3}, {%4,%5,%6,%7}, {%8,%9}, {%0,%1,%2,%3};" \
        : "+f"((d)[0]), "+f"((d)[1]), "+f"((d)[2]), "+f"((d)[3]) \
        : "r"((a)[0]), "r"((a)[1]), "r"((a)[2]), "r"((a)[3]), "r"(b0), "r"(b1))
#define CP16(d, s) asm volatile("cp.async.cg.shared.global [%0], [%1], 16;" :: "r"(d), "l"(s))
#define CP_COMMIT() asm volatile("cp.async.commit_group;" ::: "memory")
#define CP_WAIT0()  asm volatile("cp.async.wait_group 0;" ::: "memory")
#define CP_WAIT1()  asm volatile("cp.async.wait_group 1;" ::: "memory")

__device__ __forceinline__ void cvt_split2h(float x, float y, uint32_t& h, uint32_t& l) {
    __half hx = __float2half(x);
    __half hy = __float2half(y);
    __half lx = __float2half(x - __half2float(hx));
    __half ly = __float2half(y - __half2float(hy));
    h = (uint32_t)__half_as_ushort(hx) | ((uint32_t)__half_as_ushort(hy) << 16);
    l = (uint32_t)__half_as_ushort(lx) | ((uint32_t)__half_as_ushort(ly) << 16);
}
__device__ __forceinline__ uint32_t cvt2h(float x, float y) {
    return (uint32_t)__half_as_ushort(__float2half(x)) |
           ((uint32_t)__half_as_ushort(__float2half(y)) << 16);
}

// ---------------------------------------------------------------------------
// Merged prepass: split hidden + W_qkv, convert W_out, build bias table.
// ---------------------------------------------------------------------------
#define P1 (NROWS*EMB/4)
#define P2 (EMB*E3/4)
#define P3 (EMB*EMB/4)
#define PTOT (P1+P2+P3)

__global__ void prep_kernel(const float* __restrict__ hidden,
                            const float* __restrict__ wq,
                            const float* __restrict__ wo,
                            const float* __restrict__ rel_emb) {
    int i = blockIdx.x * blockDim.x + threadIdx.x;
    if (i < P1) {
        float4 a = ((const float4*)hidden)[i];
        uint32_t h01, l01, h23, l23;
        cvt_split2h(a.x, a.y, h01, l01);
        cvt_split2h(a.z, a.w, h23, l23);
        ((uint2*)g_ah)[i] = make_uint2(h01, h23);
        ((uint2*)g_al)[i] = make_uint2(l01, l23);
    } else if (i < P1 + P2) {
        int j = i - P1;
        float4 a = ((const float4*)wq)[j];
        uint32_t h01, l01, h23, l23;
        cvt_split2h(a.x, a.y, h01, l01);
        cvt_split2h(a.z, a.w, h23, l23);
        ((uint2*)g_wqh)[j] = make_uint2(h01, h23);
        ((uint2*)g_wql)[j] = make_uint2(l01, l23);
    } else if (i < PTOT) {
        int j = i - P1 - P2;
        float4 a = ((const float4*)wo)[j];
        ((uint2*)g_woh)[j] = make_uint2(cvt2h(a.x, a.y), cvt2h(a.z, a.w));
    } else {
        int j = i - PTOT;
        if (j >= NBIAS) return;
        int d  = j - (SEQ - 1);
        int rb = (d > 0) ? 16 : 0;
        int ad = d < 0 ? -d : d;
        int bucket;
        if (ad < 8) bucket = ad;
        else {
            float v  = logf((float)ad * 0.125f) / 2.7725887f;
            int   lg = 8 + (int)(v * 8.0f);
            bucket = lg < 15 ? lg : 15;
        }
        int idx = rb + bucket;
        #pragma unroll
        for (int h = 0; h < NH; h++)
            g_bias[h * NBP + j] = rel_emb[idx * NH + h];
    }
}

// ---------------------------------------------------------------------------
// Pipelined fp16 GEMM body. TERMS in {1,2,3}:
//   1: C = AhBh      2: + AlBh      3: + AhBl
// STAGES in {2,3}. 128x128 tile, BK=32, 8 warps.
// ---------------------------------------------------------------------------
template<int TERMS>
struct GLay {
    static constexpr uint32_t AH = 0;
    static constexpr uint32_t AL = 10240;                        // valid if TERMS>=2
    static constexpr uint32_t BH = (TERMS >= 2) ? 20480 : 10240;
    static constexpr uint32_t BL = BH + 8704;                    // valid if TERMS==3
    static constexpr uint32_t SSZ = BH + 8704u * (TERMS == 3 ? 2 : 1);
};

#define QKV_SMEM 87552u   // max(2*37888, 3*29184)
#define OUT_SMEM 56832u   // 3*18944

template<int TERMS>
__device__ __forceinline__ void gemm_issue(
    uint32_t base, const __half* Ah, const __half* Al,
    const __half* Bh, const __half* Bl,
    int k0, int K, int N, int tid)
{
    using L = GLay<TERMS>;
    #pragma unroll
    for (int t = 0; t < 2; t++) {
        int i = tid + t * 256;
        int r = i >> 2, c = i & 3;                 // A: 128 rows x 4 chunks
        uint32_t off = r * 80 + c * 16;
        size_t so = (size_t)r * K + k0 + c * 8;
        CP16(base + L::AH + off, Ah + so);
        if (TERMS >= 2) CP16(base + L::AL + off, Al + so);
    }
    #pragma unroll
    for (int t = 0; t < 2; t++) {
        int i = tid + t * 256;
        int r = i >> 4, c = i & 15;                // B: 32 rows x 16 chunks
        uint32_t off = r * 272 + c * 16;
        size_t so = (size_t)(k0 + r) * N + c * 8;
        CP16(base + L::BH + off, Bh + so);
        if (TERMS == 3) CP16(base + L::BL + off, Bl + so);
    }
}

template<int TERMS, int STAGES>
__device__ __forceinline__ void gemm_body(
    const __half* __restrict__ Ah, const __half* __restrict__ Al,
    const __half* __restrict__ Bh, const __half* __restrict__ Bl,
    int K, int N, size_t n0, float* __restrict__ Cf,
    __half* __restrict__ Ch, __half* __restrict__ Cl)
{
    using L = GLay<TERMS>;
    extern __shared__ __align__(16) uint8_t smem[];
    const uint32_t sb = smem_u32(smem);
    const int tid = threadIdx.x, wid = tid >> 5, lane = tid & 31;
    const int wm = wid & 3, wn = wid >> 2;
    const size_t m0 = (size_t)blockIdx.y * 128;

    const __half* Ahp = Ah + m0 * K;
    const __half* Alp = (TERMS >= 2) ? (Al + m0 * K) : nullptr;
    const __half* Bhp = Bh + n0;
    const __half* Blp = (TERMS == 3) ? (Bl + n0) : nullptr;

    float acc[2][8][4];
    #pragma unroll
    for (int i = 0; i < 2; i++)
        #pragma unroll
        for (int j = 0; j < 8; j++)
            #pragma unroll
            for (int r = 0; r < 4; r++) acc[i][j][r] = 0.f;

    const uint32_t a_fb = (wm * 32 + (lane & 15)) * 80 + (lane >> 4) * 16;
    const uint32_t b_fb = L::BH + (lane & 15) * 272 + wn * 128 + (lane >> 4) * 16;

    const int niter = K >> 5;
    #pragma unroll
    for (int p = 0; p < STAGES - 1; p++) {
        gemm_issue<TERMS>(sb + p * L::SSZ, Ahp, Alp, Bhp, Blp, p << 5, K, N, tid);
        CP_COMMIT();
    }

    for (int it = 0; it < niter; it++) {
        if (STAGES == 3 && it + 2 <= niter) CP_WAIT1(); else CP_WAIT0();
        __syncthreads();
        if (it + STAGES - 1 < niter) {
            gemm_issue<TERMS>(sb + ((it + STAGES - 1) % STAGES) * L::SSZ,
                              Ahp, Alp, Bhp, Blp, (it + STAGES - 1) << 5, K, N, tid);
            CP_COMMIT();
        }
        const uint32_t st = sb + (it % STAGES) * L::SSZ;

        #pragma unroll
        for (int ks = 0; ks < 2; ks++) {
            uint32_t ah[2][4], al[2][4];
            #pragma unroll
            for (int i = 0; i < 2; i++) {
                uint32_t aa = st + a_fb + i * 16 * 80 + ks * 32;
                LDSM_X4(ah[i], aa + L::AH);
                if (TERMS >= 2) LDSM_X4(al[i], aa + L::AL);
            }
            #pragma unroll
            for (int nh = 0; nh < 2; nh++) {
                #pragma unroll
                for (int j16 = 0; j16 < 2; j16++) {
                    uint32_t ba = st + b_fb + ks * 16 * 272 + nh * 64 + j16 * 32;
                    uint32_t bh[4];
                    LDSM_X4T(bh, ba);
                    int nf = nh * 4 + j16 * 2;
                    #pragma unroll
                    for (int i = 0; i < 2; i++) {
                        MMA16816(acc[i][nf],     ah[i], bh[0], bh[1]);
                        MMA16816(acc[i][nf + 1], ah[i], bh[2], bh[3]);
                        if (TERMS >= 2) {
                            MMA16816(acc[i][nf],     al[i], bh[0], bh[1]);
                            MMA16816(acc[i][nf + 1], al[i], bh[2], bh[3]);
                        }
                    }
                    if (TERMS == 3) {
                        uint32_t bl[4];
                        LDSM_X4T(bl, ba + (L::BL - L::BH));
                        #pragma unroll
                        for (int i = 0; i < 2; i++) {
                            MMA16816(acc[i][nf],     ah[i], bl[0], bl[1]);
                            MMA16816(acc[i][nf + 1], ah[i], bl[2], bl[3]);
                        }
                    }
                }
            }
        }
    }

    const int row_in = lane >> 2, col_in = (lane & 3) * 2;
    if (Cf) {
        #pragma unroll
        for (int i = 0; i < 2; i++)
            #pragma unroll
            for (int nf = 0; nf < 8; nf++) {
                float* p = Cf + (m0 + wm * 32 + i * 16 + row_in) * N + n0 + wn * 64 + nf * 8 + col_in;
                *(float2*)p                   = make_float2(acc[i][nf][0], acc[i][nf][1]);
                *(float2*)(p + 8 * (size_t)N) = make_float2(acc[i][nf][2], acc[i][nf][3]);
            }
    } else {
        #pragma unroll
        for (int i = 0; i < 2; i++)
            #pragma unroll
            for (int nf = 0; nf < 8; nf++) {
                size_t o = (m0 + wm * 32 + i * 16 + row_in) * N + n0 + wn * 64 + nf * 8 + col_in;
                uint32_t h01, l01, h23, l23;
                cvt_split2h(acc[i][nf][0], acc[i][nf][1], h01, l01);
                cvt_split2h(acc[i][nf][2], acc[i][nf][3], h23, l23);
                *(uint32_t*)(Ch + o) = h01;
                *(uint32_t*)(Ch + o + 8 * (size_t)N) = h23;
                if (Cl) {
                    *(uint32_t*)(Cl + o) = l01;
                    *(uint32_t*)(Cl + o + 8 * (size_t)N) = l23;
                }
            }
    }
}

// Merged QKV: blockIdx.x<16 -> Q,K cols 3-term depth-2; else V cols 2-term depth-3.
__global__ __launch_bounds__(256, 2) void qkv_kernel(
    const __half* __restrict__ Ah, const __half* __restrict__ Al,
    const __half* __restrict__ Bh, const __half* __restrict__ Bl,
    __half* __restrict__ Ch, __half* __restrict__ Cl)
{
    size_t n0 = (size_t)blockIdx.x * 128;
    if (blockIdx.x < 16)
        gemm_body<3, 2>(Ah, Al, Bh, Bl, EMB, E3, n0, nullptr, Ch, Cl);
    else
        gemm_body<2, 3>(Ah, Al, Bh, nullptr, EMB, E3, n0, nullptr, Ch, nullptr);
}

// Out-projection: 1-term depth-3 -> fp32.
__global__ __launch_bounds__(256, 2) void outproj_kernel(
    const __half* __restrict__ Ah, const __half* __restrict__ Bh,
    float* __restrict__ Cf)
{
    gemm_body<1, 3>(Ah, nullptr, Bh, nullptr, EMB, EMB,
                    (size_t)blockIdx.x * 128, Cf, nullptr, nullptr);
}

// ---------------------------------------------------------------------------
// fp16 HMMA flash attention: QK 3-term (Qh/Ql x Kh + Qh x Kl), PV 1-term.
// Block: 128 q-rows of one (b,h), 8 warps, cp.async double-buffered K/V+bias.
// (Exact R14 configuration — the 484.5us champion.)
// ---------------------------------------------------------------------------
#define KV_KH 0
#define KV_KL 9216
#define KV_VH 18432
#define KV_BIAS 27648
#define KV_STG 28672
#define AQ_H (2*KV_STG)             // 57344
#define AQ_L (AQ_H + 18432)
#define ATTN_SMEM (AQ_L + 18432)    // 94208

__device__ __forceinline__ void attn_issue(
    uint32_t base, const __half* kh, const __half* kl, const __half* vh,
    const float* biasrc, int tid)
{
    #pragma unroll
    for (int t = 0; t < 2; t++) {
        int i = tid + t * 256;
        int r = i >> 3, c = i & 7;                 // 64 rows x 8 chunks
        uint32_t off = r * 144 + c * 16;
        size_t so = (size_t)r * E3 + c * 8;
        CP16(base + KV_KH + off, kh + so);
        CP16(base + KV_KL + off, kl + so);
        CP16(base + KV_VH + off, vh + so);
    }
    if (tid < 48) CP16(base + KV_BIAS + tid * 16, biasrc + tid * 4);
}

__global__ __launch_bounds__(256, 2) void attn_mma_kernel() {
    extern __shared__ __align__(16) uint8_t sm8[];
    const uint32_t sb = smem_u32(sm8);
    const int tid = threadIdx.x, wid = tid >> 5, lane = tid & 31;
    const int q0 = blockIdx.x * 128;
    const int b = blockIdx.y >> 4, h = blockIdx.y & 15;
    const size_t rowbase = (size_t)b * SEQ;
    const float* bias_h = g_bias + h * NBP;

    // ---- stage Q hi/lo (plain copies) ----
    const __half* Qh = g_qkv_h + (rowbase + q0) * E3 + h * HD;
    const __half* Ql = g_qkv_l + (rowbase + q0) * E3 + h * HD;
    #pragma unroll
    for (int t = 0; t < 4; t++) {
        int i = tid + t * 256;
        int r = i >> 3, c = i & 7;
        uint32_t off = r * 144 + c * 16;
        size_t so = (size_t)r * E3 + c * 8;
        *(uint4*)(sm8 + AQ_H + off) = *(const uint4*)(Qh + so);
        *(uint4*)(sm8 + AQ_L + off) = *(const uint4*)(Ql + so);
    }

    // ---- prologue: issue kv tile 0 ----
    const __half* Kh0 = g_qkv_h + rowbase * E3 + EMB + h * HD;
    const __half* Kl0 = g_qkv_l + rowbase * E3 + EMB + h * HD;
    attn_issue(sb, Kh0, Kl0, Kh0 + EMB, bias_h - q0 + 1920, tid);
    CP_COMMIT();

    __syncthreads();
    // ---- hoist Q fragments ----
    uint32_t qh[4][4], ql[4][4];
    {
        uint32_t qa = sb + (wid * 16 + (lane & 15)) * 144 + (lane >> 4) * 16;
        #pragma unroll
        for (int ks = 0; ks < 4; ks++) {
            LDSM_X4(qh[ks], qa + AQ_H + ks * 32);
            LDSM_X4(ql[ks], qa + AQ_L + ks * 32);
        }
    }

    float m0 = -INFINITY, m1 = -INFINITY, l0 = 0.f, l1 = 0.f;
    float o[8][4];
    #pragma unroll
    for (int j = 0; j < 8; j++)
        #pragma unroll
        for (int r = 0; r < 4; r++) o[j][r] = 0.f;

    const uint32_t kv_fb = (lane & 15) * 144 + (lane >> 4) * 16;
    const int ccol = (lane & 3) * 2;
    const int r0 = wid * 16 + (lane >> 2);
    const int r1 = r0 + 8;

    for (int kt = 0; kt < SEQ / 64; kt++) {
        CP_WAIT0();
        __syncthreads();
        if (kt + 1 < SEQ / 64) {
            const __half* Khn = g_qkv_h + (rowbase + (kt + 1) * 64) * E3 + EMB + h * HD;
            const __half* Kln = g_qkv_l + (rowbase + (kt + 1) * 64) * E3 + EMB + h * HD;
            attn_issue(sb + ((kt + 1) & 1) * KV_STG, Khn, Kln, Khn + EMB,
                       bias_h + (kt + 1) * 64 - q0 + 1920, tid);
            CP_COMMIT();
        }
        const uint32_t st = sb + (kt & 1) * KV_STG;
        const float* sbias = (const float*)(sm8 + (kt & 1) * KV_STG + KV_BIAS);

        // ---- S = Q @ K^T (3-term) ----
        float s[8][4];
        #pragma unroll
        for (int j = 0; j < 8; j++)
            #pragma unroll
            for (int r = 0; r < 4; r++) s[j][r] = 0.f;

        #pragma unroll
        for (int ks = 0; ks < 4; ks++) {
            #pragma unroll
            for (int nb = 0; nb < 4; nb++) {
                uint32_t kh[4], kl[4];
                uint32_t ka = st + kv_fb + nb * 16 * 144 + ks * 32;
                LDSM_X4(kh, ka + KV_KH);
                LDSM_X4(kl, ka + KV_KL);
                MMA16816(s[2*nb],   qh[ks], kh[0], kh[2]);
                MMA16816(s[2*nb+1], qh[ks], kh[1], kh[3]);
                MMA16816(s[2*nb],   ql[ks], kh[0], kh[2]);
                MMA16816(s[2*nb+1], ql[ks], kh[1], kh[3]);
                MMA16816(s[2*nb],   qh[ks], kl[0], kl[2]);
                MMA16816(s[2*nb+1], qh[ks], kl[1], kl[3]);
            }
        }

        // ---- bias + online softmax ----
        float mx0 = -INFINITY, mx1 = -INFINITY;
        #pragma unroll
        for (int j = 0; j < 8; j++) {
            int c = j * 8 + ccol;
            s[j][0] += sbias[c - r0 + 127];
            s[j][1] += sbias[c + 1 - r0 + 127];
            s[j][2] += sbias[c - r1 + 127];
            s[j][3] += sbias[c + 1 - r1 + 127];
            mx0 = fmaxf(mx0, fmaxf(s[j][0], s[j][1]));
            mx1 = fmaxf(mx1, fmaxf(s[j][2], s[j][3]));
        }
        mx0 = fmaxf(mx0, __shfl_xor_sync(0xffffffffu, mx0, 1));
        mx0 = fmaxf(mx0, __shfl_xor_sync(0xffffffffu, mx0, 2));
        mx1 = fmaxf(mx1, __shfl_xor_sync(0xffffffffu, mx1, 1));
        mx1 = fmaxf(mx1, __shfl_xor_sync(0xffffffffu, mx1, 2));
        float m0n = fmaxf(m0, mx0), m1n = fmaxf(m1, mx1);
        float c0 = exp2f((m0 - m0n) * L2E), c1 = exp2f((m1 - m1n) * L2E);
        float rs0 = 0.f, rs1 = 0.f;
        #pragma unroll
        for (int j = 0; j < 8; j++) {
            s[j][0] = exp2f((s[j][0] - m0n) * L2E);
            s[j][1] = exp2f((s[j][1] - m0n) * L2E);
            s[j][2] = exp2f((s[j][2] - m1n) * L2E);
            s[j][3] = exp2f((s[j][3] - m1n) * L2E);
            rs0 += s[j][0] + s[j][1];
            rs1 += s[j][2] + s[j][3];
        }
        rs0 += __shfl_xor_sync(0xffffffffu, rs0, 1);
        rs0 += __shfl_xor_sync(0xffffffffu, rs0, 2);
        rs1 += __shfl_xor_sync(0xffffffffu, rs1, 1);
        rs1 += __shfl_xor_sync(0xffffffffu, rs1, 2);
        l0 = l0 * c0 + rs0; l1 = l1 * c1 + rs1;
        m0 = m0n; m1 = m1n;
        #pragma unroll
        for (int j = 0; j < 8; j++) {
            o[j][0] *= c0; o[j][1] *= c0; o[j][2] *= c1; o[j][3] *= c1;
        }

        // ---- O += P @ V (1-term, P hi only) ----
        #pragma unroll
        for (int t = 0; t < 4; t++) {
            uint32_t ap[4];
            ap[0] = cvt2h(s[2*t][0],   s[2*t][1]);
            ap[1] = cvt2h(s[2*t][2],   s[2*t][3]);
            ap[2] = cvt2h(s[2*t+1][0], s[2*t+1][1]);
            ap[3] = cvt2h(s[2*t+1][2], s[2*t+1][3]);
            #pragma unroll
            for (int g = 0; g < 4; g++) {
                uint32_t vh[4];
                LDSM_X4T(vh, st + kv_fb + t * 16 * 144 + g * 32 + KV_VH);
                MMA16816(o[2*g],   ap, vh[0], vh[1]);
                MMA16816(o[2*g+1], ap, vh[2], vh[3]);
            }
        }
    }

    // ---- epilogue: hi-only fp16 out ----
    float inv0 = 1.f / l0, inv1 = 1.f / l1;
    size_t ob = (rowbase + q0 + r0) * EMB + h * HD + ccol;
    #pragma unroll
    for (int j = 0; j < 8; j++) {
        *(uint32_t*)(g_attn_h + ob + j * 8)           = cvt2h(o[j][0] * inv0, o[j][1] * inv0);
        *(uint32_t*)(g_attn_h + ob + 8 * EMB + j * 8) = cvt2h(o[j][2] * inv1, o[j][3] * inv1);
    }
}

// ---------------------------------------------------------------------------
extern "C" void kernel_launch(void* const* d_in, const int* in_sizes, int n_in,
                              void* d_out, int out_size) {
    const float* hidden = (const float*)d_in[0];
    const float* W_qkv  = (const float*)d_in[1];
    const float* W_out  = (const float*)d_in[2];
    const float* rel    = (const float*)d_in[3];
    float* out = (float*)d_out;

    __half *ah, *al, *wqh, *wql, *woh, *qh, *ql, *ath;
    cudaGetSymbolAddress((void**)&ah,  g_ah);
    cudaGetSymbolAddress((void**)&al,  g_al);
    cudaGetSymbolAddress((void**)&wqh, g_wqh);
    cudaGetSymbolAddress((void**)&wql, g_wql);
    cudaGetSymbolAddress((void**)&woh, g_woh);
    cudaGetSymbolAddress((void**)&qh,  g_qkv_h);
    cudaGetSymbolAddress((void**)&ql,  g_qkv_l);
    cudaGetSymbolAddress((void**)&ath, g_attn_h);

    cudaFuncSetAttribute(qkv_kernel,
                         cudaFuncAttributeMaxDynamicSharedMemorySize, QKV_SMEM);
    cudaFuncSetAttribute(outproj_kernel,
                         cudaFuncAttributeMaxDynamicSharedMemorySize, OUT_SMEM);
    cudaFuncSetAttribute(attn_mma_kernel,
                         cudaFuncAttributeMaxDynamicSharedMemorySize, ATTN_SMEM);

    prep_kernel<<<(PTOT + NBIAS + 255) / 256, 256>>>(hidden, W_qkv, W_out, rel);

    qkv_kernel<<<dim3(E3 / 128, NROWS / 128), 256, QKV_SMEM>>>(
        ah, al, wqh, wql, qh, ql);

    attn_mma_kernel<<<dim3(SEQ / 128, BATCH * NH), 256, ATTN_SMEM>>>();

    outproj_kernel<<<dim3(EMB / 128, NROWS / 128), 256, OUT_SMEM>>>(
        ath, woh, out);
}